// round 16
// baseline (speedup 1.0000x reference)
#include <cuda_runtime.h>
#include <cuda_fp16.h>
#include <math.h>
#include <stdint.h>

#define NN 50000
#define EE 600000
#define DDIM 128
#define NTILES ((NN + 127) / 128)   // 391
#define PGRID 148
#define ENC_GRID 296
#define NSB ((NN + 255) / 256)      // 196

// ---------------- scratch ----------------
__device__ uint32_t g_xah[(size_t)NN * 64];
__device__ uint32_t g_xbh[(size_t)NN * 64];
__device__ uint32_t g_aggh[(size_t)2 * NN * 64];
__device__ int    g_deg[NN];
__device__ int    g_tmp[NN];
__device__ int    g_bsum[NSB];
__device__ int    g_rowptr[NN + 1];
__device__ int    g_cur[NN];
__device__ int    g_ebuf[EE];
__device__ double g_sums[4];
__device__ int    g_barrier;

__device__ __forceinline__ float lrelu(float x) { return x > 0.f ? x : 0.01f * x; }

__device__ __forceinline__ uint32_t pk(float a, float b) {
    __half2 h = __floats2half2_rn(a, b);
    return *reinterpret_cast<uint32_t*>(&h);
}
__device__ __forceinline__ float2 upk(uint32_t w) {
    __half2 h = *reinterpret_cast<__half2*>(&w);
    return __half22float2(h);
}
__device__ __forceinline__ uint32_t aff(uint32_t w, float2 s, float2 h) {
    float2 f = upk(w);
    return pk(fmaf(f.x, s.x, h.x), fmaf(f.y, s.y, h.y));
}

__device__ __forceinline__ void mma_f16(float c[4], uint32_t a0, uint32_t a1,
                                        uint32_t a2, uint32_t a3,
                                        uint32_t b0, uint32_t b1) {
    asm volatile(
        "mma.sync.aligned.m16n8k16.row.col.f32.f16.f16.f32 "
        "{%0,%1,%2,%3},{%4,%5,%6,%7},{%8,%9},{%0,%1,%2,%3};"
        : "+f"(c[0]), "+f"(c[1]), "+f"(c[2]), "+f"(c[3])
        : "r"(a0), "r"(a1), "r"(a2), "r"(a3), "r"(b0), "r"(b1));
}

__device__ __forceinline__ void lda16(const uint32_t* sA, int P, int row, int kp0, int v,
                                      uint32_t& a0, uint32_t& a1, uint32_t& a2, uint32_t& a3) {
    const uint32_t* p = sA + row * P + kp0 + v;
    a0 = p[0]; a1 = p[8 * P]; a2 = p[4]; a3 = p[8 * P + 4];
}

__device__ __forceinline__ void ldb16(const uint32_t* sW, int P, int kp0, int n0, int u, int v,
                                      uint32_t& b0, uint32_t& b1) {
    int col = (n0 + u) ^ (v << 3);
    b0 = sW[(kp0 + v) * P + col];
    b1 = sW[(kp0 + v + 4) * P + col];
}

__device__ __forceinline__ void cvtw(uint32_t* sW, int P, const float* W, int N, int kp, int n4) {
    float4 f0 = __ldg((const float4*)(W + (size_t)(2 * kp) * N + n4));
    float4 f1 = __ldg((const float4*)(W + (size_t)(2 * kp + 1) * N + n4));
    uint4 w;
    w.x = pk(f0.x, f1.x); w.y = pk(f0.y, f1.y);
    w.z = pk(f0.z, f1.z); w.w = pk(f0.w, f1.w);
    *(uint4*)(sW + kp * P + (n4 ^ ((kp & 3) << 3))) = w;
}

__device__ __forceinline__ void ln_affine(const double* s, float g, float b,
                                          float& sc, float& sh) {
    const float cnt = (float)NN * (float)DDIM;
    float mu = (float)s[0] / cnt;
    float var = (float)s[1] / cnt - mu * mu;
    float rstd = rsqrtf(var + 1e-5f);
    sc = rstd * g;
    sh = b - mu * sc;
}

// ---------------- setup kernels ----------------
__global__ void init_kernel() {
    int i = blockIdx.x * blockDim.x + threadIdx.x;
    if (i < NN) g_deg[i] = 0;
    if (i < 4) g_sums[i] = 0.0;
    if (i == 0) g_barrier = 0;
}

__global__ void hist_kernel(const int* __restrict__ ei) {
    int e = blockIdx.x * blockDim.x + threadIdx.x;
    if (e < EE) atomicAdd(&g_deg[ei[EE + e]], 1);
}

__global__ void s1_kernel() {
    __shared__ int ws[8];
    const int tid = threadIdx.x, b = blockIdx.x;
    const int lane = tid & 31, wid = tid >> 5;
    int i = b * 256 + tid;
    int v = (i < NN) ? g_deg[i] : 0;
    int x = v;
    #pragma unroll
    for (int o = 1; o < 32; o <<= 1) {
        int y = __shfl_up_sync(0xFFFFFFFFu, x, o);
        if (lane >= o) x += y;
    }
    if (lane == 31) ws[wid] = x;
    __syncthreads();
    if (wid == 0) {
        int s = (lane < 8) ? ws[lane] : 0;
        #pragma unroll
        for (int o = 1; o < 8; o <<= 1) {
            int y = __shfl_up_sync(0xFFFFFFFFu, s, o);
            if (lane >= o) s += y;
        }
        if (lane < 8) ws[lane] = s;
    }
    __syncthreads();
    int incl = x + (wid > 0 ? ws[wid - 1] : 0);
    if (i < NN) g_tmp[i] = incl;
    if (tid == 255) g_bsum[b] = incl;
}

__global__ void s23_kernel() {
    __shared__ int s_off;
    const int b = blockIdx.x, tid = threadIdx.x;
    if (tid < 32) {
        int acc = 0;
        for (int j = tid; j < b; j += 32) acc += g_bsum[j];
        #pragma unroll
        for (int o = 16; o; o >>= 1) acc += __shfl_down_sync(0xFFFFFFFFu, acc, o);
        if (tid == 0) s_off = acc;
    }
    __syncthreads();
    int i = b * 256 + tid;
    if (i < NN) {
        int r = g_tmp[i] + s_off;
        g_rowptr[i + 1] = r;
        g_cur[i] = r - g_deg[i];
    }
    if (i == 0) g_rowptr[0] = 0;
}

__global__ void fill_kernel(const int* __restrict__ ei, const int* __restrict__ et) {
    int e = blockIdx.x * blockDim.x + threadIdx.x;
    if (e >= EE) return;
    int src = ei[e];
    int dst = ei[EE + e];
    int pos = atomicAdd(&g_cur[dst], 1);
    g_ebuf[pos] = src | (et[e] << 30);
}

// ---------------- encode (2 CTAs/SM, persistent: grid=ENC_GRID, tile loop) -------------
__global__ void __launch_bounds__(256, 2) encode_kernel(
    const float* __restrict__ desc, const float* __restrict__ tweet,
    const float* __restrict__ numf, const float* __restrict__ catf,
    const float* __restrict__ Wd, const float* __restrict__ bd,
    const float* __restrict__ Wt, const float* __restrict__ bt,
    const float* __restrict__ Wn, const float* __restrict__ bn,
    const float* __restrict__ Wc, const float* __restrict__ bc,
    const float* __restrict__ W1, const float* __restrict__ b1,
    uint32_t* __restrict__ outh)
{
    extern __shared__ uint32_t S[];
    uint32_t* sW  = S;
    uint32_t* sX0 = S + 12288;
    uint32_t* sA0 = S + 20992;
    uint32_t* sA1 = S + 23552;
    float*    sNC = (float*)(S + 26112);

    const int tid = threadIdx.x;
    const int lane = tid & 31, warp = tid >> 5;
    const int u = lane >> 2, v = lane & 3;
    const int r0 = warp * 16;
    const int srow = tid >> 3, sc4 = (tid & 7) * 4;

    if (tid < 160) sNC[tid] = Wn[tid];
    if (tid < 96)  sNC[160 + tid] = Wc[tid];
    if (tid < 32)  { sNC[256 + tid] = bn[tid]; sNC[288 + tid] = bc[tid]; }

    for (int tile = blockIdx.x; tile < NTILES; tile += ENC_GRID) {
        const int node0 = tile * 128;
        __syncthreads();   // prior tile's smem consumers done before sW overwrite

        for (int ph = 0; ph < 2; ph++) {
            const float* In = ph ? tweet : desc;
            const float* W  = ph ? Wt : Wd;
            const float* B  = ph ? bt : bd;

            for (int i = tid; i < 3072; i += 256) cvtw(sW, 32, W, 32, i >> 3, (i & 7) * 4);

            float acc[4][4];
            #pragma unroll
            for (int nt = 0; nt < 4; nt++) {
                float2 bv = *(const float2*)(B + nt * 8 + 2 * v);
                acc[nt][0] = bv.x; acc[nt][1] = bv.y; acc[nt][2] = bv.x; acc[nt][3] = bv.y;
            }

            float4 pvA[4], pvB[4];
            #pragma unroll
            for (int j = 0; j < 4; j++) {
                int g = node0 + srow + j * 32;
                pvA[j] = make_float4(0.f, 0.f, 0.f, 0.f);
                pvB[j] = make_float4(0.f, 0.f, 0.f, 0.f);
                if (g < NN) {
                    pvA[j] = __ldg((const float4*)(In + (size_t)g * 768 + sc4));
                    pvB[j] = __ldg((const float4*)(In + (size_t)g * 768 + 32 + sc4));
                }
            }
            #pragma unroll
            for (int j = 0; j < 4; j++) {
                uint2 w; w.x = pk(pvA[j].x, pvA[j].y); w.y = pk(pvA[j].z, pvA[j].w);
                *(uint2*)(sA0 + (srow + j * 32) * 20 + (sc4 >> 1)) = w;
            }
            __syncthreads();

            #define ENC_ITER(CI, PVL, PVS, SRC, DST)                                        \
            {                                                                                \
                if ((CI) + 2 < 24) {                                                         \
                    _Pragma("unroll")                                                        \
                    for (int j = 0; j < 4; j++) {                                            \
                        int g = node0 + srow + j * 32;                                       \
                        PVL[j] = make_float4(0.f, 0.f, 0.f, 0.f);                            \
                        if (g < NN)                                                          \
                            PVL[j] = __ldg((const float4*)(In + (size_t)g * 768              \
                                                           + ((CI) + 2) * 32 + sc4));        \
                    }                                                                        \
                }                                                                            \
                if ((CI) + 1 < 24) {                                                         \
                    _Pragma("unroll")                                                        \
                    for (int j = 0; j < 4; j++) {                                            \
                        uint2 w; w.x = pk(PVS[j].x, PVS[j].y); w.y = pk(PVS[j].z, PVS[j].w); \
                        *(uint2*)((DST) + (srow + j * 32) * 20 + (sc4 >> 1)) = w;            \
                    }                                                                        \
                }                                                                            \
                _Pragma("unroll")                                                            \
                for (int ks = 0; ks < 2; ks++) {                                             \
                    uint32_t a0, a1, a2, a3;                                                 \
                    lda16((SRC), 20, r0 + u, ks * 8, v, a0, a1, a2, a3);                     \
                    int kp0 = (CI) * 16 + ks * 8;                                            \
                    _Pragma("unroll")                                                        \
                    for (int nt = 0; nt < 4; nt++) {                                         \
                        uint32_t b0, b1;                                                     \
                        ldb16(sW, 32, kp0, nt * 8, u, v, b0, b1);                            \
                        mma_f16(acc[nt], a0, a1, a2, a3, b0, b1);                            \
                    }                                                                        \
                }                                                                            \
                __syncthreads();                                                             \
            }

            for (int cc = 0; cc < 24; cc += 2) {
                ENC_ITER(cc,     pvA, pvB, sA0, sA1);
                ENC_ITER(cc + 1, pvB, pvA, sA1, sA0);
            }
            #undef ENC_ITER

            const int cb2 = ph * 16;
            #pragma unroll
            for (int nt = 0; nt < 4; nt++) {
                int kp = cb2 + nt * 4 + v;
                sX0[(r0 + u) * 68 + kp]     = pk(lrelu(acc[nt][0]), lrelu(acc[nt][1]));
                sX0[(r0 + u + 8) * 68 + kp] = pk(lrelu(acc[nt][2]), lrelu(acc[nt][3]));
            }
        }

        __syncthreads();
        {
            __half* sX0h = (__half*)sX0;
            for (int o = tid; o < 8192; o += 256) {
                int row = o >> 6, c = o & 63;
                int g = node0 + row;
                float vv = 0.f;
                if (g < NN) {
                    if (c < 32) {
                        float a = sNC[256 + c];
                        #pragma unroll
                        for (int k = 0; k < 5; k++)
                            a = fmaf(__ldg(numf + (size_t)g * 5 + k), sNC[k * 32 + c], a);
                        vv = lrelu(a);
                    } else {
                        int cc = c - 32;
                        float a = sNC[288 + cc];
                        #pragma unroll
                        for (int k = 0; k < 3; k++)
                            a = fmaf(__ldg(catf + (size_t)g * 3 + k), sNC[160 + k * 32 + cc], a);
                        vv = lrelu(a);
                    }
                }
                sX0h[row * 136 + 64 + c] = __float2half(vv);
            }
        }
        for (int i = tid; i < 2048; i += 256) cvtw(sW, 128, W1, 128, i >> 5, (i & 31) * 4);
        __syncthreads();

        {
            float acc[16][4];
            #pragma unroll
            for (int nt = 0; nt < 16; nt++) {
                float2 bv = *(const float2*)(b1 + nt * 8 + 2 * v);
                acc[nt][0] = bv.x; acc[nt][1] = bv.y; acc[nt][2] = bv.x; acc[nt][3] = bv.y;
            }
            #pragma unroll
            for (int ks = 0; ks < 8; ks++) {
                uint32_t a0, a1, a2, a3;
                lda16(sX0, 68, r0 + u, ks * 8, v, a0, a1, a2, a3);
                #pragma unroll
                for (int nt = 0; nt < 16; nt++) {
                    uint32_t b0, b1;
                    ldb16(sW, 128, ks * 8, nt * 8, u, v, b0, b1);
                    mma_f16(acc[nt], a0, a1, a2, a3, b0, b1);
                }
            }
            int gA = node0 + r0 + u, gB = gA + 8;
            #pragma unroll
            for (int nt = 0; nt < 16; nt++) {
                int wofs = nt * 4 + v;
                if (gA < NN)
                    outh[(size_t)gA * 64 + wofs] = pk(lrelu(acc[nt][0]), lrelu(acc[nt][1]));
                if (gB < NN)
                    outh[(size_t)gB * 64 + wofs] = pk(lrelu(acc[nt][2]), lrelu(acc[nt][3]));
            }
        }
    }
}

// ---------------- pull (fp16 gather, warp/node, inline LN affine, unroll 4; PDL) --------
__global__ void pull_kernel(const uint32_t* __restrict__ xh,
                            const double* __restrict__ sums_in,
                            const float* __restrict__ lng,
                            const float* __restrict__ lnb,
                            int apply) {
    cudaGridDependencySynchronize();

    const int w = (blockIdx.x * blockDim.x + threadIdx.x) >> 5;
    const int lane = threadIdx.x & 31;
    if (w >= NN) return;
    float4 sc = make_float4(1.f, 1.f, 1.f, 1.f);
    float4 sh = make_float4(0.f, 0.f, 0.f, 0.f);
    if (apply) {
        float4 g4 = __ldg((const float4*)lng + lane);
        float4 b4 = __ldg((const float4*)lnb + lane);
        ln_affine(sums_in, g4.x, b4.x, sc.x, sh.x);
        ln_affine(sums_in, g4.y, b4.y, sc.y, sh.y);
        ln_affine(sums_in, g4.z, b4.z, sc.z, sh.z);
        ln_affine(sums_in, g4.w, b4.w, sc.w, sh.w);
    }
    const int beg = g_rowptr[w], end = g_rowptr[w + 1];
    const float NEG = -3.0e38f;
    float4 a0 = make_float4(NEG, NEG, NEG, NEG);
    float4 a1 = a0;

    #define PULL_ONE(VE)                                                             \
    {                                                                                 \
        uint2 d = __ldg((const uint2*)(xh + (size_t)((VE) & 0x3FFFFFFF) * 64) + lane);\
        float2 fx = upk(d.x), fy = upk(d.y);                                          \
        float4 f;                                                                     \
        f.x = fmaf(fx.x, sc.x, sh.x); f.y = fmaf(fx.y, sc.y, sh.y);                   \
        f.z = fmaf(fy.x, sc.z, sh.z); f.w = fmaf(fy.y, sc.w, sh.w);                   \
        if ((VE) >> 30) {                                                             \
            a1.x = fmaxf(a1.x, f.x); a1.y = fmaxf(a1.y, f.y);                         \
            a1.z = fmaxf(a1.z, f.z); a1.w = fmaxf(a1.w, f.w);                         \
        } else {                                                                      \
            a0.x = fmaxf(a0.x, f.x); a0.y = fmaxf(a0.y, f.y);                         \
            a0.z = fmaxf(a0.z, f.z); a0.w = fmaxf(a0.w, f.w);                         \
        }                                                                             \
    }

    int e = beg;
    for (; e + 4 <= end; e += 4) {
        int v0 = g_ebuf[e], v1 = g_ebuf[e + 1], v2 = g_ebuf[e + 2], v3 = g_ebuf[e + 3];
        PULL_ONE(v0); PULL_ONE(v1); PULL_ONE(v2); PULL_ONE(v3);
    }
    for (; e < end; e++) { int v0 = g_ebuf[e]; PULL_ONE(v0); }
    #undef PULL_ONE

    uint2 o0, o1;
    o0.x = pk((a0.x == NEG) ? 0.f : a0.x, (a0.y == NEG) ? 0.f : a0.y);
    o0.y = pk((a0.z == NEG) ? 0.f : a0.z, (a0.w == NEG) ? 0.f : a0.w);
    o1.x = pk((a1.x == NEG) ? 0.f : a1.x, (a1.y == NEG) ? 0.f : a1.y);
    o1.y = pk((a1.z == NEG) ? 0.f : a1.z, (a1.w == NEG) ? 0.f : a1.w);
    ((uint2*)(g_aggh + (size_t)w * 64))[lane] = o0;
    ((uint2*)(g_aggh + (size_t)(NN + w) * 64))[lane] = o1;
}

// ---------------- RGCN GEMM (round-14: 16x128 warp tile, persistent, direct-LDG A,
//                  2-step prefetch, PDL prologue; fused head after grid barrier) --------
// smem words: sW 24576 | sSc 128 | sSh 128 | sw3 128 = 24960 (99840 B)
__global__ void __launch_bounds__(256, 1) rgcn_kernel(
    const uint32_t* __restrict__ xh,
    const float* __restrict__ root,
    const float* __restrict__ relw,
    const float* __restrict__ bias,
    const double* __restrict__ sums_in,
    const float* __restrict__ lng,
    const float* __restrict__ lnb,
    int apply,
    uint32_t* __restrict__ outh,
    double* __restrict__ sums_out,
    const float* __restrict__ W2,
    const float* __restrict__ b2,
    const float* __restrict__ W3f,
    const float* __restrict__ b3,
    const float* __restrict__ lng2,
    const float* __restrict__ lnb2,
    float* __restrict__ outp,
    int do_head)
{
    extern __shared__ uint32_t S[];
    uint32_t* sW = S;
    float2* sSc = (float2*)(S + 24576);
    float2* sSh = (float2*)(S + 24704);
    float*  sw3 = (float*)(S + 24832);
    __shared__ double sred[2];
    const int tid = threadIdx.x;
    const int lane = tid & 31, warp = tid >> 5;
    const int u = lane >> 2, v = lane & 3;
    const int r0 = warp * 16;
    if (tid < 2) sred[tid] = 0.0;

    for (int i = tid; i < 2048; i += 256) cvtw(sW, 128, root, 128, i >> 5, (i & 31) * 4);
    for (int i = tid; i < 4096; i += 256)
        cvtw(sW + 64 * 128, 128, relw, 128, i >> 5, (i & 31) * 4);

    cudaGridDependencySynchronize();

    if (apply && tid < 64) {
        float2 g2 = __ldg((const float2*)lng + tid);
        float2 b2v = __ldg((const float2*)lnb + tid);
        float2 sc, sh;
        ln_affine(sums_in, g2.x, b2v.x, sc.x, sh.x);
        ln_affine(sums_in, g2.y, b2v.y, sc.y, sh.y);
        sSc[tid] = sc; sSh[tid] = sh;
    }
    __syncthreads();

    for (int tile = blockIdx.x; tile < NTILES; tile += PGRID) {
        const int node0 = tile * 128;
        const int gA = node0 + r0 + u, gB = gA + 8;
        const bool okA = gA < NN, okB = gB < NN;

        float acc[16][4];
        #pragma unroll
        for (int nt = 0; nt < 16; nt++) {
            float2 bv = *(const float2*)(bias + nt * 8 + 2 * v);
            acc[nt][0] = bv.x; acc[nt][1] = bv.y; acc[nt][2] = bv.x; acc[nt][3] = bv.y;
        }

        #define LOAD_FRAG(S_, F_)                                                      \
        {                                                                               \
            int part = (S_) >> 3;                                                       \
            const uint32_t* base = (part == 0) ? xh : g_aggh;                           \
            size_t ofs = (part == 2) ? (size_t)NN * 64 : 0;                             \
            int w0 = (((S_) & 7) << 3) + v;                                             \
            F_[0] = okA ? __ldg(base + ofs + (size_t)gA * 64 + w0)     : 0u;            \
            F_[2] = okA ? __ldg(base + ofs + (size_t)gA * 64 + w0 + 4) : 0u;            \
            F_[1] = okB ? __ldg(base + ofs + (size_t)gB * 64 + w0)     : 0u;            \
            F_[3] = okB ? __ldg(base + ofs + (size_t)gB * 64 + w0 + 4) : 0u;            \
            if (apply && part == 0) {                                                   \
                float2 s0 = sSc[w0],     h0 = sSh[w0];                                  \
                float2 s1 = sSc[w0 + 4], h1 = sSh[w0 + 4];                              \
                F_[0] = aff(F_[0], s0, h0); F_[1] = aff(F_[1], s0, h0);                 \
                F_[2] = aff(F_[2], s1, h1); F_[3] = aff(F_[3], s1, h1);                 \
            }                                                                           \
        }

        uint32_t f0[4], f1[4];
        LOAD_FRAG(0, f0);
        LOAD_FRAG(1, f1);
        #pragma unroll
        for (int s = 0; s < 24; s++) {
            uint32_t fn[4];
            if (s + 2 < 24) LOAD_FRAG(s + 2, fn);
            #pragma unroll
            for (int nt = 0; nt < 16; nt++) {
                uint32_t b0, b1;
                ldb16(sW, 128, s * 8, nt * 8, u, v, b0, b1);
                mma_f16(acc[nt], f0[0], f0[1], f0[2], f0[3], b0, b1);
            }
            #pragma unroll
            for (int q = 0; q < 4; q++) { f0[q] = f1[q]; f1[q] = fn[q]; }
        }
        #undef LOAD_FRAG

        float ls = 0.f, lq = 0.f;
        #pragma unroll
        for (int nt = 0; nt < 16; nt++) {
            int wofs = nt * 4 + v;
            if (okA) {
                float x0 = acc[nt][0], x1 = acc[nt][1];
                outh[(size_t)gA * 64 + wofs] = pk(x0, x1);
                ls += x0 + x1; lq += x0 * x0 + x1 * x1;
            }
            if (okB) {
                float x0 = acc[nt][2], x1 = acc[nt][3];
                outh[(size_t)gB * 64 + wofs] = pk(x0, x1);
                ls += x0 + x1; lq += x0 * x0 + x1 * x1;
            }
        }
        #pragma unroll
        for (int off = 16; off; off >>= 1) {
            ls += __shfl_down_sync(0xFFFFFFFFu, ls, off);
            lq += __shfl_down_sync(0xFFFFFFFFu, lq, off);
        }
        if (lane == 0) {
            atomicAdd(&sred[0], (double)ls);
            atomicAdd(&sred[1], (double)lq);
        }
    }

    __syncthreads();
    if (tid == 0) {
        atomicAdd(&sums_out[0], sred[0]);
        atomicAdd(&sums_out[1], sred[1]);
    }

    if (!do_head) return;

    if (tid == 0) {
        __threadfence();
        atomicAdd(&g_barrier, 1);
        while (atomicAdd(&g_barrier, 0) < PGRID) {}
    }
    __syncthreads();

    for (int i = tid; i < 2048; i += 256) cvtw(sW, 128, W2, 128, i >> 5, (i & 31) * 4);
    if (tid < 128) sw3[tid] = W3f[tid];
    if (tid < 64) {
        float2 g2 = __ldg((const float2*)lng2 + tid);
        float2 b2v = __ldg((const float2*)lnb2 + tid);
        float2 sc, sh;
        ln_affine(sums_out, g2.x, b2v.x, sc.x, sh.x);
        ln_affine(sums_out, g2.y, b2v.y, sc.y, sh.y);
        sSc[tid] = sc; sSh[tid] = sh;
    }
    __syncthreads();

    for (int tile = blockIdx.x; tile < NTILES; tile += PGRID) {
        const int node0 = tile * 128;
        const int gA = node0 + r0 + u, gB = gA + 8;
        const bool okA = gA < NN, okB = gB < NN;

        float acc[16][4];
        #pragma unroll
        for (int nt = 0; nt < 16; nt++) {
            float2 bv = *(const float2*)(b2 + nt * 8 + 2 * v);
            acc[nt][0] = bv.x; acc[nt][1] = bv.y; acc[nt][2] = bv.x; acc[nt][3] = bv.y;
        }
        #pragma unroll
        for (int s = 0; s < 8; s++) {
            int w0 = s * 8 + v;
            uint32_t f0 = okA ? __ldg(outh + (size_t)gA * 64 + w0)     : 0u;
            uint32_t f2 = okA ? __ldg(outh + (size_t)gA * 64 + w0 + 4) : 0u;
            uint32_t f1 = okB ? __ldg(outh + (size_t)gB * 64 + w0)     : 0u;
            uint32_t f3 = okB ? __ldg(outh + (size_t)gB * 64 + w0 + 4) : 0u;
            float2 s0 = sSc[w0], h0 = sSh[w0];
            float2 s1 = sSc[w0 + 4], h1 = sSh[w0 + 4];
            f0 = aff(f0, s0, h0); f1 = aff(f1, s0, h0);
            f2 = aff(f2, s1, h1); f3 = aff(f3, s1, h1);
            #pragma unroll
            for (int nt = 0; nt < 16; nt++) {
                uint32_t b0, b1;
                ldb16(sW, 128, s * 8, nt * 8, u, v, b0, b1);
                mma_f16(acc[nt], f0, f1, f2, f3, b0, b1);
            }
        }

        float pA = 0.f, pB = 0.f;
        #pragma unroll
        for (int nt = 0; nt < 16; nt++) {
            int col = nt * 8 + 2 * v;
            float w0 = sw3[col], w1 = sw3[col + 1];
            pA += lrelu(acc[nt][0]) * w0 + lrelu(acc[nt][1]) * w1;
            pB += lrelu(acc[nt][2]) * w0 + lrelu(acc[nt][3]) * w1;
        }
        pA += __shfl_xor_sync(0xFFFFFFFFu, pA, 1);
        pA += __shfl_xor_sync(0xFFFFFFFFu, pA, 2);
        pB += __shfl_xor_sync(0xFFFFFFFFu, pB, 1);
        pB += __shfl_xor_sync(0xFFFFFFFFu, pB, 2);
        if (v == 0) {
            float b3v = __ldg(b3);
            if (okA) outp[gA] = 1.f / (1.f + expf(-(pA + b3v)));
            if (okB) outp[gB] = 1.f / (1.f + expf(-(pB + b3v)));
        }
    }
}

// ---------------- launch ----------------
extern "C" void kernel_launch(void* const* d_in, const int* in_sizes, int n_in,
                              void* d_out, int out_size)
{
    const float* desc  = (const float*)d_in[0];
    const float* tweet = (const float*)d_in[1];
    const float* numf  = (const float*)d_in[2];
    const float* catf  = (const float*)d_in[3];
    const int*   ei    = (const int*)d_in[4];
    const int*   et    = (const int*)d_in[5];
    const float* Wd = (const float*)d_in[6];  const float* bd = (const float*)d_in[7];
    const float* Wt = (const float*)d_in[8];  const float* bt = (const float*)d_in[9];
    const float* Wn = (const float*)d_in[10]; const float* bn = (const float*)d_in[11];
    const float* Wc = (const float*)d_in[12]; const float* bc = (const float*)d_in[13];
    const float* W1 = (const float*)d_in[14]; const float* b1 = (const float*)d_in[15];
    const float* rg1_w    = (const float*)d_in[16];
    const float* rg1_root = (const float*)d_in[17];
    const float* rg1_bias = (const float*)d_in[18];
    const float* ln1_g = (const float*)d_in[19]; const float* ln1_b = (const float*)d_in[20];
    const float* rg2_w    = (const float*)d_in[21];
    const float* rg2_root = (const float*)d_in[22];
    const float* rg2_bias = (const float*)d_in[23];
    const float* ln2_g = (const float*)d_in[24]; const float* ln2_b = (const float*)d_in[25];
    const float* W2 = (const float*)d_in[26]; const float* b2 = (const float*)d_in[27];
    const float* W3 = (const float*)d_in[28]; const float* b3 = (const float*)d_in[29];

    uint32_t *xah, *xbh;
    double* sums;
    cudaGetSymbolAddress((void**)&xah, g_xah);
    cudaGetSymbolAddress((void**)&xbh, g_xbh);
    cudaGetSymbolAddress((void**)&sums, g_sums);

    const int SM_ENC  = 26432 * 4;                 // 105728
    const int SM_RGCN = 24960 * 4;                 // 99840
    cudaFuncSetAttribute(encode_kernel, cudaFuncAttributeMaxDynamicSharedMemorySize, SM_ENC);
    cudaFuncSetAttribute(rgcn_kernel,   cudaFuncAttributeMaxDynamicSharedMemorySize, SM_RGCN);

    static cudaStream_t side = nullptr;
    static cudaEvent_t evFork = nullptr, evJoin = nullptr;
    if (side == nullptr) {
        cudaStreamCreateWithFlags(&side, cudaStreamNonBlocking);
        cudaEventCreateWithFlags(&evFork, cudaEventDisableTiming);
        cudaEventCreateWithFlags(&evJoin, cudaEventDisableTiming);
    }

    cudaEventRecord(evFork, 0);
    cudaStreamWaitEvent(side, evFork, 0);
    init_kernel<<<(NN + 255) / 256, 256, 0, side>>>();
    hist_kernel<<<(EE + 255) / 256, 256, 0, side>>>(ei);
    s1_kernel<<<NSB, 256, 0, side>>>();
    s23_kernel<<<NSB, 256, 0, side>>>();
    fill_kernel<<<(EE + 255) / 256, 256, 0, side>>>(ei, et);
    cudaEventRecord(evJoin, side);

    encode_kernel<<<ENC_GRID, 256, SM_ENC>>>(desc, tweet, numf, catf,
                                             Wd, bd, Wt, bt, Wn, bn, Wc, bc,
                                             W1, b1, xah);
    cudaStreamWaitEvent(0, evJoin, 0);

    cudaLaunchAttribute pdl[1];
    pdl[0].id = cudaLaunchAttributeProgrammaticStreamSerialization;
    pdl[0].val.programmaticStreamSerializationAllowed = 1;

    {
        cudaLaunchConfig_t cfg = {};
        cfg.gridDim = dim3((NN + 7) / 8);
        cfg.blockDim = dim3(256);
        cfg.stream = 0;
        cfg.attrs = pdl; cfg.numAttrs = 1;
        cudaLaunchKernelEx(&cfg, pull_kernel,
                           (const uint32_t*)xah, (const double*)sums, ln1_g, ln1_b, 0);
    }
    {
        cudaLaunchConfig_t cfg = {};
        cfg.gridDim = dim3(PGRID);
        cfg.blockDim = dim3(256);
        cfg.dynamicSmemBytes = SM_RGCN;
        cfg.stream = 0;
        cfg.attrs = pdl; cfg.numAttrs = 1;
        cudaLaunchKernelEx(&cfg, rgcn_kernel,
                           (const uint32_t*)xah, rg1_root, rg1_w, rg1_bias,
                           (const double*)sums, ln1_g, ln1_b, 0,
                           (uint32_t*)xbh, (double*)(sums + 0),
                           W2, b2, W3, b3, ln2_g, ln2_b, (float*)d_out, 0);
    }
    {
        cudaLaunchConfig_t cfg = {};
        cfg.gridDim = dim3((NN + 7) / 8);
        cfg.blockDim = dim3(256);
        cfg.stream = 0;
        cfg.attrs = pdl; cfg.numAttrs = 1;
        cudaLaunchKernelEx(&cfg, pull_kernel,
                           (const uint32_t*)xbh, (const double*)(sums + 0), ln1_g, ln1_b, 1);
    }
    {
        cudaLaunchConfig_t cfg = {};
        cfg.gridDim = dim3(PGRID);
        cfg.blockDim = dim3(256);
        cfg.dynamicSmemBytes = SM_RGCN;
        cfg.stream = 0;
        cfg.attrs = pdl; cfg.numAttrs = 1;
        cudaLaunchKernelEx(&cfg, rgcn_kernel,
                           (const uint32_t*)xbh, rg2_root, rg2_w, rg2_bias,
                           (const double*)(sums + 0), ln1_g, ln1_b, 1,
                           (uint32_t*)xah, (double*)(sums + 2),
                           W2, b2, W3, b3, ln2_g, ln2_b, (float*)d_out, 1);
    }
}

// round 17
// speedup vs baseline: 1.2359x; 1.2359x over previous
#include <cuda_runtime.h>
#include <cuda_fp16.h>
#include <math.h>
#include <stdint.h>

#define NN 50000
#define EE 600000
#define DDIM 128
#define NTILES ((NN + 127) / 128)   // 391
#define PGRID 148
#define NSB ((NN + 255) / 256)      // 196

// ---------------- scratch ----------------
__device__ uint32_t g_xah[(size_t)NN * 64];
__device__ uint32_t g_xbh[(size_t)NN * 64];
__device__ uint32_t g_aggh[(size_t)2 * NN * 64];
__device__ int    g_deg[NN];
__device__ int    g_tmp[NN];
__device__ int    g_bsum[NSB];
__device__ int    g_rowptr[NN + 1];
__device__ int    g_cur[NN];
__device__ int    g_ebuf[EE];
__device__ double g_sums[4];
__device__ int    g_barrier;

__device__ __forceinline__ float lrelu(float x) { return x > 0.f ? x : 0.01f * x; }

__device__ __forceinline__ uint32_t pk(float a, float b) {
    __half2 h = __floats2half2_rn(a, b);
    return *reinterpret_cast<uint32_t*>(&h);
}
__device__ __forceinline__ float2 upk(uint32_t w) {
    __half2 h = *reinterpret_cast<__half2*>(&w);
    return __half22float2(h);
}
__device__ __forceinline__ uint32_t aff(uint32_t w, float2 s, float2 h) {
    float2 f = upk(w);
    return pk(fmaf(f.x, s.x, h.x), fmaf(f.y, s.y, h.y));
}

__device__ __forceinline__ void mma_f16(float c[4], uint32_t a0, uint32_t a1,
                                        uint32_t a2, uint32_t a3,
                                        uint32_t b0, uint32_t b1) {
    asm volatile(
        "mma.sync.aligned.m16n8k16.row.col.f32.f16.f16.f32 "
        "{%0,%1,%2,%3},{%4,%5,%6,%7},{%8,%9},{%0,%1,%2,%3};"
        : "+f"(c[0]), "+f"(c[1]), "+f"(c[2]), "+f"(c[3])
        : "r"(a0), "r"(a1), "r"(a2), "r"(a3), "r"(b0), "r"(b1));
}

__device__ __forceinline__ void lda16(const uint32_t* sA, int P, int row, int kp0, int v,
                                      uint32_t& a0, uint32_t& a1, uint32_t& a2, uint32_t& a3) {
    const uint32_t* p = sA + row * P + kp0 + v;
    a0 = p[0]; a1 = p[8 * P]; a2 = p[4]; a3 = p[8 * P + 4];
}

__device__ __forceinline__ void ldb16(const uint32_t* sW, int P, int kp0, int n0, int u, int v,
                                      uint32_t& b0, uint32_t& b1) {
    int col = (n0 + u) ^ (v << 3);
    b0 = sW[(kp0 + v) * P + col];
    b1 = sW[(kp0 + v + 4) * P + col];
}

__device__ __forceinline__ void cvtw(uint32_t* sW, int P, const float* W, int N, int kp, int n4) {
    float4 f0 = __ldg((const float4*)(W + (size_t)(2 * kp) * N + n4));
    float4 f1 = __ldg((const float4*)(W + (size_t)(2 * kp + 1) * N + n4));
    uint4 w;
    w.x = pk(f0.x, f1.x); w.y = pk(f0.y, f1.y);
    w.z = pk(f0.z, f1.z); w.w = pk(f0.w, f1.w);
    *(uint4*)(sW + kp * P + (n4 ^ ((kp & 3) << 3))) = w;
}

__device__ __forceinline__ void ln_affine(const double* s, float g, float b,
                                          float& sc, float& sh) {
    const float cnt = (float)NN * (float)DDIM;
    float mu = (float)s[0] / cnt;
    float var = (float)s[1] / cnt - mu * mu;
    float rstd = rsqrtf(var + 1e-5f);
    sc = rstd * g;
    sh = b - mu * sc;
}

// ---------------- setup kernels ----------------
__global__ void init_kernel() {
    int i = blockIdx.x * blockDim.x + threadIdx.x;
    if (i < NN) g_deg[i] = 0;
    if (i < 4) g_sums[i] = 0.0;
    if (i == 0) g_barrier = 0;
}

__global__ void hist_kernel(const int* __restrict__ ei) {
    int e = blockIdx.x * blockDim.x + threadIdx.x;
    if (e < EE) atomicAdd(&g_deg[ei[EE + e]], 1);
}

__global__ void s1_kernel() {
    __shared__ int ws[8];
    const int tid = threadIdx.x, b = blockIdx.x;
    const int lane = tid & 31, wid = tid >> 5;
    int i = b * 256 + tid;
    int v = (i < NN) ? g_deg[i] : 0;
    int x = v;
    #pragma unroll
    for (int o = 1; o < 32; o <<= 1) {
        int y = __shfl_up_sync(0xFFFFFFFFu, x, o);
        if (lane >= o) x += y;
    }
    if (lane == 31) ws[wid] = x;
    __syncthreads();
    if (wid == 0) {
        int s = (lane < 8) ? ws[lane] : 0;
        #pragma unroll
        for (int o = 1; o < 8; o <<= 1) {
            int y = __shfl_up_sync(0xFFFFFFFFu, s, o);
            if (lane >= o) s += y;
        }
        if (lane < 8) ws[lane] = s;
    }
    __syncthreads();
    int incl = x + (wid > 0 ? ws[wid - 1] : 0);
    if (i < NN) g_tmp[i] = incl;
    if (tid == 255) g_bsum[b] = incl;
}

__global__ void s23_kernel() {
    __shared__ int s_off;
    const int b = blockIdx.x, tid = threadIdx.x;
    if (tid < 32) {
        int acc = 0;
        for (int j = tid; j < b; j += 32) acc += g_bsum[j];
        #pragma unroll
        for (int o = 16; o; o >>= 1) acc += __shfl_down_sync(0xFFFFFFFFu, acc, o);
        if (tid == 0) s_off = acc;
    }
    __syncthreads();
    int i = b * 256 + tid;
    if (i < NN) {
        int r = g_tmp[i] + s_off;
        g_rowptr[i + 1] = r;
        g_cur[i] = r - g_deg[i];
    }
    if (i == 0) g_rowptr[0] = 0;
}

__global__ void fill_kernel(const int* __restrict__ ei, const int* __restrict__ et) {
    int e = blockIdx.x * blockDim.x + threadIdx.x;
    if (e >= EE) return;
    int src = ei[e];
    int dst = ei[EE + e];
    int pos = atomicAdd(&g_cur[dst], 1);
    g_ebuf[pos] = src | (et[e] << 30);
}

// ---------------- encode (2 CTAs/SM) ----------------
__global__ void __launch_bounds__(256, 2) encode_kernel(
    const float* __restrict__ desc, const float* __restrict__ tweet,
    const float* __restrict__ numf, const float* __restrict__ catf,
    const float* __restrict__ Wd, const float* __restrict__ bd,
    const float* __restrict__ Wt, const float* __restrict__ bt,
    const float* __restrict__ Wn, const float* __restrict__ bn,
    const float* __restrict__ Wc, const float* __restrict__ bc,
    const float* __restrict__ W1, const float* __restrict__ b1,
    uint32_t* __restrict__ outh)
{
    extern __shared__ uint32_t S[];
    uint32_t* sW  = S;
    uint32_t* sX0 = S + 12288;
    uint32_t* sA0 = S + 20992;
    uint32_t* sA1 = S + 23552;
    float*    sNC = (float*)(S + 26112);

    const int tid = threadIdx.x;
    const int node0 = blockIdx.x * 128;
    const int lane = tid & 31, warp = tid >> 5;
    const int u = lane >> 2, v = lane & 3;
    const int r0 = warp * 16;
    const int srow = tid >> 3, sc4 = (tid & 7) * 4;

    if (tid < 160) sNC[tid] = Wn[tid];
    if (tid < 96)  sNC[160 + tid] = Wc[tid];
    if (tid < 32)  { sNC[256 + tid] = bn[tid]; sNC[288 + tid] = bc[tid]; }

    for (int ph = 0; ph < 2; ph++) {
        const float* In = ph ? tweet : desc;
        const float* W  = ph ? Wt : Wd;
        const float* B  = ph ? bt : bd;

        for (int i = tid; i < 3072; i += 256) cvtw(sW, 32, W, 32, i >> 3, (i & 7) * 4);

        float acc[4][4];
        #pragma unroll
        for (int nt = 0; nt < 4; nt++) {
            float2 bv = *(const float2*)(B + nt * 8 + 2 * v);
            acc[nt][0] = bv.x; acc[nt][1] = bv.y; acc[nt][2] = bv.x; acc[nt][3] = bv.y;
        }

        float4 pvA[4], pvB[4];
        #pragma unroll
        for (int j = 0; j < 4; j++) {
            int g = node0 + srow + j * 32;
            pvA[j] = make_float4(0.f, 0.f, 0.f, 0.f);
            pvB[j] = make_float4(0.f, 0.f, 0.f, 0.f);
            if (g < NN) {
                pvA[j] = __ldg((const float4*)(In + (size_t)g * 768 + sc4));
                pvB[j] = __ldg((const float4*)(In + (size_t)g * 768 + 32 + sc4));
            }
        }
        #pragma unroll
        for (int j = 0; j < 4; j++) {
            uint2 w; w.x = pk(pvA[j].x, pvA[j].y); w.y = pk(pvA[j].z, pvA[j].w);
            *(uint2*)(sA0 + (srow + j * 32) * 20 + (sc4 >> 1)) = w;
        }
        __syncthreads();

        #define ENC_ITER(CI, PVL, PVS, SRC, DST)                                        \
        {                                                                                \
            if ((CI) + 2 < 24) {                                                         \
                _Pragma("unroll")                                                        \
                for (int j = 0; j < 4; j++) {                                            \
                    int g = node0 + srow + j * 32;                                       \
                    PVL[j] = make_float4(0.f, 0.f, 0.f, 0.f);                            \
                    if (g < NN)                                                          \
                        PVL[j] = __ldg((const float4*)(In + (size_t)g * 768              \
                                                       + ((CI) + 2) * 32 + sc4));        \
                }                                                                        \
            }                                                                            \
            if ((CI) + 1 < 24) {                                                         \
                _Pragma("unroll")                                                        \
                for (int j = 0; j < 4; j++) {                                            \
                    uint2 w; w.x = pk(PVS[j].x, PVS[j].y); w.y = pk(PVS[j].z, PVS[j].w); \
                    *(uint2*)((DST) + (srow + j * 32) * 20 + (sc4 >> 1)) = w;            \
                }                                                                        \
            }                                                                            \
            _Pragma("unroll")                                                            \
            for (int ks = 0; ks < 2; ks++) {                                             \
                uint32_t a0, a1, a2, a3;                                                 \
                lda16((SRC), 20, r0 + u, ks * 8, v, a0, a1, a2, a3);                     \
                int kp0 = (CI) * 16 + ks * 8;                                            \
                _Pragma("unroll")                                                        \
                for (int nt = 0; nt < 4; nt++) {                                         \
                    uint32_t b0, b1;                                                     \
                    ldb16(sW, 32, kp0, nt * 8, u, v, b0, b1);                            \
                    mma_f16(acc[nt], a0, a1, a2, a3, b0, b1);                            \
                }                                                                        \
            }                                                                            \
            __syncthreads();                                                             \
        }

        for (int cc = 0; cc < 24; cc += 2) {
            ENC_ITER(cc,     pvA, pvB, sA0, sA1);
            ENC_ITER(cc + 1, pvB, pvA, sA1, sA0);
        }
        #undef ENC_ITER

        const int cb2 = ph * 16;
        #pragma unroll
        for (int nt = 0; nt < 4; nt++) {
            int kp = cb2 + nt * 4 + v;
            sX0[(r0 + u) * 68 + kp]     = pk(lrelu(acc[nt][0]), lrelu(acc[nt][1]));
            sX0[(r0 + u + 8) * 68 + kp] = pk(lrelu(acc[nt][2]), lrelu(acc[nt][3]));
        }
    }

    __syncthreads();
    {
        __half* sX0h = (__half*)sX0;
        for (int o = tid; o < 8192; o += 256) {
            int row = o >> 6, c = o & 63;
            int g = node0 + row;
            float vv = 0.f;
            if (g < NN) {
                if (c < 32) {
                    float a = sNC[256 + c];
                    #pragma unroll
                    for (int k = 0; k < 5; k++)
                        a = fmaf(__ldg(numf + (size_t)g * 5 + k), sNC[k * 32 + c], a);
                    vv = lrelu(a);
                } else {
                    int cc = c - 32;
                    float a = sNC[288 + cc];
                    #pragma unroll
                    for (int k = 0; k < 3; k++)
                        a = fmaf(__ldg(catf + (size_t)g * 3 + k), sNC[160 + k * 32 + cc], a);
                    vv = lrelu(a);
                }
            }
            sX0h[row * 136 + 64 + c] = __float2half(vv);
        }
    }
    for (int i = tid; i < 2048; i += 256) cvtw(sW, 128, W1, 128, i >> 5, (i & 31) * 4);
    __syncthreads();

    {
        float acc[16][4];
        #pragma unroll
        for (int nt = 0; nt < 16; nt++) {
            float2 bv = *(const float2*)(b1 + nt * 8 + 2 * v);
            acc[nt][0] = bv.x; acc[nt][1] = bv.y; acc[nt][2] = bv.x; acc[nt][3] = bv.y;
        }
        #pragma unroll
        for (int ks = 0; ks < 8; ks++) {
            uint32_t a0, a1, a2, a3;
            lda16(sX0, 68, r0 + u, ks * 8, v, a0, a1, a2, a3);
            #pragma unroll
            for (int nt = 0; nt < 16; nt++) {
                uint32_t b0, b1;
                ldb16(sW, 128, ks * 8, nt * 8, u, v, b0, b1);
                mma_f16(acc[nt], a0, a1, a2, a3, b0, b1);
            }
        }
        int gA = node0 + r0 + u, gB = gA + 8;
        #pragma unroll
        for (int nt = 0; nt < 16; nt++) {
            int wofs = nt * 4 + v;
            if (gA < NN)
                outh[(size_t)gA * 64 + wofs] = pk(lrelu(acc[nt][0]), lrelu(acc[nt][1]));
            if (gB < NN)
                outh[(size_t)gB * 64 + wofs] = pk(lrelu(acc[nt][2]), lrelu(acc[nt][3]));
        }
    }
}

// ---------------- pull (fp16 gather, warp/node, inline LN affine, unroll 4; PDL) --------
__global__ void pull_kernel(const uint32_t* __restrict__ xh,
                            const double* __restrict__ sums_in,
                            const float* __restrict__ lng,
                            const float* __restrict__ lnb,
                            int apply) {
    cudaGridDependencySynchronize();

    const int w = (blockIdx.x * blockDim.x + threadIdx.x) >> 5;
    const int lane = threadIdx.x & 31;
    if (w >= NN) return;
    float4 sc = make_float4(1.f, 1.f, 1.f, 1.f);
    float4 sh = make_float4(0.f, 0.f, 0.f, 0.f);
    if (apply) {
        float4 g4 = __ldg((const float4*)lng + lane);
        float4 b4 = __ldg((const float4*)lnb + lane);
        ln_affine(sums_in, g4.x, b4.x, sc.x, sh.x);
        ln_affine(sums_in, g4.y, b4.y, sc.y, sh.y);
        ln_affine(sums_in, g4.z, b4.z, sc.z, sh.z);
        ln_affine(sums_in, g4.w, b4.w, sc.w, sh.w);
    }
    const int beg = g_rowptr[w], end = g_rowptr[w + 1];
    const float NEG = -3.0e38f;
    float4 a0 = make_float4(NEG, NEG, NEG, NEG);
    float4 a1 = a0;

    #define PULL_ONE(VE)                                                             \
    {                                                                                 \
        uint2 d = __ldg((const uint2*)(xh + (size_t)((VE) & 0x3FFFFFFF) * 64) + lane);\
        float2 fx = upk(d.x), fy = upk(d.y);                                          \
        float4 f;                                                                     \
        f.x = fmaf(fx.x, sc.x, sh.x); f.y = fmaf(fx.y, sc.y, sh.y);                   \
        f.z = fmaf(fy.x, sc.z, sh.z); f.w = fmaf(fy.y, sc.w, sh.w);                   \
        if ((VE) >> 30) {                                                             \
            a1.x = fmaxf(a1.x, f.x); a1.y = fmaxf(a1.y, f.y);                         \
            a1.z = fmaxf(a1.z, f.z); a1.w = fmaxf(a1.w, f.w);                         \
        } else {                                                                      \
            a0.x = fmaxf(a0.x, f.x); a0.y = fmaxf(a0.y, f.y);                         \
            a0.z = fmaxf(a0.z, f.z); a0.w = fmaxf(a0.w, f.w);                         \
        }                                                                             \
    }

    int e = beg;
    for (; e + 4 <= end; e += 4) {
        int v0 = g_ebuf[e], v1 = g_ebuf[e + 1], v2 = g_ebuf[e + 2], v3 = g_ebuf[e + 3];
        PULL_ONE(v0); PULL_ONE(v1); PULL_ONE(v2); PULL_ONE(v3);
    }
    for (; e < end; e++) { int v0 = g_ebuf[e]; PULL_ONE(v0); }
    #undef PULL_ONE

    uint2 o0, o1;
    o0.x = pk((a0.x == NEG) ? 0.f : a0.x, (a0.y == NEG) ? 0.f : a0.y);
    o0.y = pk((a0.z == NEG) ? 0.f : a0.z, (a0.w == NEG) ? 0.f : a0.w);
    o1.x = pk((a1.x == NEG) ? 0.f : a1.x, (a1.y == NEG) ? 0.f : a1.y);
    o1.y = pk((a1.z == NEG) ? 0.f : a1.z, (a1.w == NEG) ? 0.f : a1.w);
    ((uint2*)(g_aggh + (size_t)w * 64))[lane] = o0;
    ((uint2*)(g_aggh + (size_t)(NN + w) * 64))[lane] = o1;
}

// ---------------- RGCN GEMM (legacy mma, persistent, direct-LDG A, 2-step prefetch,
//                  PDL prologue; optional fused head after a grid-wide barrier) ---------
// smem words: sW 24576 | sSc 128 | sSh 128 | sw3 128 = 24960 (99840 B)
__global__ void __launch_bounds__(256, 1) rgcn_kernel(
    const uint32_t* __restrict__ xh,
    const float* __restrict__ root,
    const float* __restrict__ relw,
    const float* __restrict__ bias,
    const double* __restrict__ sums_in,
    const float* __restrict__ lng,
    const float* __restrict__ lnb,
    int apply,
    uint32_t* __restrict__ outh,
    double* __restrict__ sums_out,
    const float* __restrict__ W2,
    const float* __restrict__ b2,
    const float* __restrict__ W3f,
    const float* __restrict__ b3,
    const float* __restrict__ lng2,
    const float* __restrict__ lnb2,
    float* __restrict__ outp,
    int do_head)
{
    extern __shared__ uint32_t S[];
    uint32_t* sW = S;
    float2* sSc = (float2*)(S + 24576);
    float2* sSh = (float2*)(S + 24704);
    float*  sw3 = (float*)(S + 24832);
    __shared__ double sred[2];
    const int tid = threadIdx.x;
    const int lane = tid & 31, warp = tid >> 5;
    const int u = lane >> 2, v = lane & 3;
    const int r0 = warp * 16;
    if (tid < 2) sred[tid] = 0.0;

    // PDL prologue: weight conversion (kernel inputs only)
    for (int i = tid; i < 2048; i += 256) cvtw(sW, 128, root, 128, i >> 5, (i & 31) * 4);
    for (int i = tid; i < 4096; i += 256)
        cvtw(sW + 64 * 128, 128, relw, 128, i >> 5, (i & 31) * 4);

    cudaGridDependencySynchronize();

    if (apply && tid < 64) {
        float2 g2 = __ldg((const float2*)lng + tid);
        float2 b2v = __ldg((const float2*)lnb + tid);
        float2 sc, sh;
        ln_affine(sums_in, g2.x, b2v.x, sc.x, sh.x);
        ln_affine(sums_in, g2.y, b2v.y, sc.y, sh.y);
        sSc[tid] = sc; sSh[tid] = sh;
    }
    __syncthreads();

    for (int tile = blockIdx.x; tile < NTILES; tile += PGRID) {
        const int node0 = tile * 128;
        const int gA = node0 + r0 + u, gB = gA + 8;
        const bool okA = gA < NN, okB = gB < NN;

        float acc[16][4];
        #pragma unroll
        for (int nt = 0; nt < 16; nt++) {
            float2 bv = *(const float2*)(bias + nt * 8 + 2 * v);
            acc[nt][0] = bv.x; acc[nt][1] = bv.y; acc[nt][2] = bv.x; acc[nt][3] = bv.y;
        }

        #define LOAD_FRAG(S_, F_)                                                      \
        {                                                                               \
            int part = (S_) >> 3;                                                       \
            const uint32_t* base = (part == 0) ? xh : g_aggh;                           \
            size_t ofs = (part == 2) ? (size_t)NN * 64 : 0;                             \
            int w0 = (((S_) & 7) << 3) + v;                                             \
            F_[0] = okA ? __ldg(base + ofs + (size_t)gA * 64 + w0)     : 0u;            \
            F_[2] = okA ? __ldg(base + ofs + (size_t)gA * 64 + w0 + 4) : 0u;            \
            F_[1] = okB ? __ldg(base + ofs + (size_t)gB * 64 + w0)     : 0u;            \
            F_[3] = okB ? __ldg(base + ofs + (size_t)gB * 64 + w0 + 4) : 0u;            \
            if (apply && part == 0) {                                                   \
                float2 s0 = sSc[w0],     h0 = sSh[w0];                                  \
                float2 s1 = sSc[w0 + 4], h1 = sSh[w0 + 4];                              \
                F_[0] = aff(F_[0], s0, h0); F_[1] = aff(F_[1], s0, h0);                 \
                F_[2] = aff(F_[2], s1, h1); F_[3] = aff(F_[3], s1, h1);                 \
            }                                                                           \
        }

        uint32_t f0[4], f1[4];
        LOAD_FRAG(0, f0);
        LOAD_FRAG(1, f1);
        #pragma unroll
        for (int s = 0; s < 24; s++) {
            uint32_t fn[4];
            if (s + 2 < 24) LOAD_FRAG(s + 2, fn);
            #pragma unroll
            for (int nt = 0; nt < 16; nt++) {
                uint32_t b0, b1;
                ldb16(sW, 128, s * 8, nt * 8, u, v, b0, b1);
                mma_f16(acc[nt], f0[0], f0[1], f0[2], f0[3], b0, b1);
            }
            #pragma unroll
            for (int q = 0; q < 4; q++) { f0[q] = f1[q]; f1[q] = fn[q]; }
        }
        #undef LOAD_FRAG

        float ls = 0.f, lq = 0.f;
        #pragma unroll
        for (int nt = 0; nt < 16; nt++) {
            int wofs = nt * 4 + v;
            if (okA) {
                float x0 = acc[nt][0], x1 = acc[nt][1];
                outh[(size_t)gA * 64 + wofs] = pk(x0, x1);
                ls += x0 + x1; lq += x0 * x0 + x1 * x1;
            }
            if (okB) {
                float x0 = acc[nt][2], x1 = acc[nt][3];
                outh[(size_t)gB * 64 + wofs] = pk(x0, x1);
                ls += x0 + x1; lq += x0 * x0 + x1 * x1;
            }
        }
        #pragma unroll
        for (int off = 16; off; off >>= 1) {
            ls += __shfl_down_sync(0xFFFFFFFFu, ls, off);
            lq += __shfl_down_sync(0xFFFFFFFFu, lq, off);
        }
        if (lane == 0) {
            atomicAdd(&sred[0], (double)ls);
            atomicAdd(&sred[1], (double)lq);
        }
    }

    __syncthreads();
    if (tid == 0) {
        atomicAdd(&sums_out[0], sred[0]);
        atomicAdd(&sums_out[1], sred[1]);
    }

    if (!do_head) return;

    // ---- grid-wide barrier (all PGRID blocks co-resident: 1 CTA/SM, grid=148) ----
    if (tid == 0) {
        __threadfence();
        atomicAdd(&g_barrier, 1);
        while (atomicAdd(&g_barrier, 0) < PGRID) {}
    }
    __syncthreads();

    // ---- fused head: convert W2 into sW (weights dead), LN2 affine, sigmoid out ----
    for (int i = tid; i < 2048; i += 256) cvtw(sW, 128, W2, 128, i >> 5, (i & 31) * 4);
    if (tid < 128) sw3[tid] = W3f[tid];
    if (tid < 64) {
        float2 g2 = __ldg((const float2*)lng2 + tid);
        float2 b2v = __ldg((const float2*)lnb2 + tid);
        float2 sc, sh;
        ln_affine(sums_out, g2.x, b2v.x, sc.x, sh.x);
        ln_affine(sums_out, g2.y, b2v.y, sc.y, sh.y);
        sSc[tid] = sc; sSh[tid] = sh;
    }
    __syncthreads();

    for (int tile = blockIdx.x; tile < NTILES; tile += PGRID) {
        const int node0 = tile * 128;
        const int gA = node0 + r0 + u, gB = gA + 8;
        const bool okA = gA < NN, okB = gB < NN;

        float acc[16][4];
        #pragma unroll
        for (int nt = 0; nt < 16; nt++) {
            float2 bv = *(const float2*)(b2 + nt * 8 + 2 * v);
            acc[nt][0] = bv.x; acc[nt][1] = bv.y; acc[nt][2] = bv.x; acc[nt][3] = bv.y;
        }
        #pragma unroll
        for (int s = 0; s < 8; s++) {
            int w0 = s * 8 + v;
            uint32_t f0 = okA ? __ldg(outh + (size_t)gA * 64 + w0)     : 0u;
            uint32_t f2 = okA ? __ldg(outh + (size_t)gA * 64 + w0 + 4) : 0u;
            uint32_t f1 = okB ? __ldg(outh + (size_t)gB * 64 + w0)     : 0u;
            uint32_t f3 = okB ? __ldg(outh + (size_t)gB * 64 + w0 + 4) : 0u;
            float2 s0 = sSc[w0], h0 = sSh[w0];
            float2 s1 = sSc[w0 + 4], h1 = sSh[w0 + 4];
            f0 = aff(f0, s0, h0); f1 = aff(f1, s0, h0);
            f2 = aff(f2, s1, h1); f3 = aff(f3, s1, h1);
            #pragma unroll
            for (int nt = 0; nt < 16; nt++) {
                uint32_t b0, b1;
                ldb16(sW, 128, s * 8, nt * 8, u, v, b0, b1);
                mma_f16(acc[nt], f0, f1, f2, f3, b0, b1);
            }
        }

        float pA = 0.f, pB = 0.f;
        #pragma unroll
        for (int nt = 0; nt < 16; nt++) {
            int col = nt * 8 + 2 * v;
            float w0 = sw3[col], w1 = sw3[col + 1];
            pA += lrelu(acc[nt][0]) * w0 + lrelu(acc[nt][1]) * w1;
            pB += lrelu(acc[nt][2]) * w0 + lrelu(acc[nt][3]) * w1;
        }
        pA += __shfl_xor_sync(0xFFFFFFFFu, pA, 1);
        pA += __shfl_xor_sync(0xFFFFFFFFu, pA, 2);
        pB += __shfl_xor_sync(0xFFFFFFFFu, pB, 1);
        pB += __shfl_xor_sync(0xFFFFFFFFu, pB, 2);
        if (v == 0) {
            float b3v = __ldg(b3);
            if (okA) outp[gA] = 1.f / (1.f + expf(-(pA + b3v)));
            if (okB) outp[gB] = 1.f / (1.f + expf(-(pB + b3v)));
        }
    }
}

// ---------------- launch ----------------
extern "C" void kernel_launch(void* const* d_in, const int* in_sizes, int n_in,
                              void* d_out, int out_size)
{
    const float* desc  = (const float*)d_in[0];
    const float* tweet = (const float*)d_in[1];
    const float* numf  = (const float*)d_in[2];
    const float* catf  = (const float*)d_in[3];
    const int*   ei    = (const int*)d_in[4];
    const int*   et    = (const int*)d_in[5];
    const float* Wd = (const float*)d_in[6];  const float* bd = (const float*)d_in[7];
    const float* Wt = (const float*)d_in[8];  const float* bt = (const float*)d_in[9];
    const float* Wn = (const float*)d_in[10]; const float* bn = (const float*)d_in[11];
    const float* Wc = (const float*)d_in[12]; const float* bc = (const float*)d_in[13];
    const float* W1 = (const float*)d_in[14]; const float* b1 = (const float*)d_in[15];
    const float* rg1_w    = (const float*)d_in[16];
    const float* rg1_root = (const float*)d_in[17];
    const float* rg1_bias = (const float*)d_in[18];
    const float* ln1_g = (const float*)d_in[19]; const float* ln1_b = (const float*)d_in[20];
    const float* rg2_w    = (const float*)d_in[21];
    const float* rg2_root = (const float*)d_in[22];
    const float* rg2_bias = (const float*)d_in[23];
    const float* ln2_g = (const float*)d_in[24]; const float* ln2_b = (const float*)d_in[25];
    const float* W2 = (const float*)d_in[26]; const float* b2 = (const float*)d_in[27];
    const float* W3 = (const float*)d_in[28]; const float* b3 = (const float*)d_in[29];

    uint32_t *xah, *xbh;
    double* sums;
    cudaGetSymbolAddress((void**)&xah, g_xah);
    cudaGetSymbolAddress((void**)&xbh, g_xbh);
    cudaGetSymbolAddress((void**)&sums, g_sums);

    const int SM_ENC  = 26432 * 4;                 // 105728
    const int SM_RGCN = 24960 * 4;                 // 99840
    cudaFuncSetAttribute(encode_kernel, cudaFuncAttributeMaxDynamicSharedMemorySize, SM_ENC);
    cudaFuncSetAttribute(rgcn_kernel,   cudaFuncAttributeMaxDynamicSharedMemorySize, SM_RGCN);

    static cudaStream_t side = nullptr;
    static cudaEvent_t evFork = nullptr, evJoin = nullptr;
    if (side == nullptr) {
        cudaStreamCreateWithFlags(&side, cudaStreamNonBlocking);
        cudaEventCreateWithFlags(&evFork, cudaEventDisableTiming);
        cudaEventCreateWithFlags(&evJoin, cudaEventDisableTiming);
    }

    cudaEventRecord(evFork, 0);
    cudaStreamWaitEvent(side, evFork, 0);
    init_kernel<<<(NN + 255) / 256, 256, 0, side>>>();
    hist_kernel<<<(EE + 255) / 256, 256, 0, side>>>(ei);
    s1_kernel<<<NSB, 256, 0, side>>>();
    s23_kernel<<<NSB, 256, 0, side>>>();
    fill_kernel<<<(EE + 255) / 256, 256, 0, side>>>(ei, et);
    cudaEventRecord(evJoin, side);

    encode_kernel<<<NTILES, 256, SM_ENC>>>(desc, tweet, numf, catf,
                                           Wd, bd, Wt, bt, Wn, bn, Wc, bc,
                                           W1, b1, xah);
    cudaStreamWaitEvent(0, evJoin, 0);

    cudaLaunchAttribute pdl[1];
    pdl[0].id = cudaLaunchAttributeProgrammaticStreamSerialization;
    pdl[0].val.programmaticStreamSerializationAllowed = 1;

    {
        cudaLaunchConfig_t cfg = {};
        cfg.gridDim = dim3((NN + 7) / 8);
        cfg.blockDim = dim3(256);
        cfg.stream = 0;
        cfg.attrs = pdl; cfg.numAttrs = 1;
        cudaLaunchKernelEx(&cfg, pull_kernel,
                           (const uint32_t*)xah, (const double*)sums, ln1_g, ln1_b, 0);
    }
    {
        cudaLaunchConfig_t cfg = {};
        cfg.gridDim = dim3(PGRID);
        cfg.blockDim = dim3(256);
        cfg.dynamicSmemBytes = SM_RGCN;
        cfg.stream = 0;
        cfg.attrs = pdl; cfg.numAttrs = 1;
        cudaLaunchKernelEx(&cfg, rgcn_kernel,
                           (const uint32_t*)xah, rg1_root, rg1_w, rg1_bias,
                           (const double*)sums, ln1_g, ln1_b, 0,
                           (uint32_t*)xbh, (double*)(sums + 0),
                           W2, b2, W3, b3, ln2_g, ln2_b, (float*)d_out, 0);
    }
    {
        cudaLaunchConfig_t cfg = {};
        cfg.gridDim = dim3((NN + 7) / 8);
        cfg.blockDim = dim3(256);
        cfg.stream = 0;
        cfg.attrs = pdl; cfg.numAttrs = 1;
        cudaLaunchKernelEx(&cfg, pull_kernel,
                           (const uint32_t*)xbh, (const double*)(sums + 0), ln1_g, ln1_b, 1);
    }
    {
        cudaLaunchConfig_t cfg = {};
        cfg.gridDim = dim3(PGRID);
        cfg.blockDim = dim3(256);
        cfg.dynamicSmemBytes = SM_RGCN;
        cfg.stream = 0;
        cfg.attrs = pdl; cfg.numAttrs = 1;
        cudaLaunchKernelEx(&cfg, rgcn_kernel,
                           (const uint32_t*)xbh, rg2_root, rg2_w, rg2_bias,
                           (const double*)(sums + 0), ln1_g, ln1_b, 1,
                           (uint32_t*)xah, (double*)(sums + 2),
                           W2, b2, W3, b3, ln2_g, ln2_b, (float*)d_out, 1);
    }
}